// round 17
// baseline (speedup 1.0000x reference)
#include <cuda_runtime.h>

// Problem constants
#define NN 2
#define DD 160
#define HH 192
#define WW 192
#define HW (HH * WW)

#define TILE_W 32
#define TILE_H 24          // per CTA; 3 output rows per thread (8 ty-groups)
#define HALO_W 36
#define HALO_H 28
#define ROW_BYTES 144      // halo row in a plane: 36 floats
#define PLANE_BYTES (HALO_H * ROW_BYTES)      // 4032
#define SLICE_BYTES (2 * PLANE_BYTES)         // 8064 (I + J planes)
#define PAIR_BYTES (2 * SLICE_BYTES)          // 16128
#define RING_BYTES (3 * PAIR_BYTES)           // 48384 (triple-buffered pair ring)

#define RROWH 40           // ABCD uint2 stride (bank-proven)
#define RROWE 40           // E f32 stride: bank = (8*row + c) mod 32 -> conflict-free stores
#define RS_ROWS 56         // 2 slices x 28 halo rows
#define RS4H_OFF RING_BYTES                     // 48384
#define RS4H_BYTES (2 * RS_ROWS * RROWH * 8)    // 35840
#define RS1_OFF (RS4H_OFF + RS4H_BYTES)         // 84224
#define RS1_BYTES (2 * RS_ROWS * RROWE * 4)     // 17920
#define RED_OFF (RS1_OFF + RS1_BYTES)           // 102144
#define DYN_TOTAL (RED_OFF + 32)                // 102176 (~99.8KB, x2 = 200KB/SM)

#define NTHREADS 256
#define CHUNKS_PER_ROW 18                     // 36 floats / 2 per 8B chunk
#define IPLANE_CHUNKS (HALO_H * CHUNKS_PER_ROW) // 504 per plane
#define NBLOCKS (6 * 8 * 6)                   // 288 = one wave @ occ 2

#define VINV (1.0f / 125.0f)
#define EPSV 1e-5f
#define NG2 0xBF800000BF800000ULL             // packed (-1.0f, -1.0f)

typedef unsigned long long ull;

// ---- packed f32x2 helpers ----
__device__ __forceinline__ ull pk2(float lo, float hi) {
    ull r; asm("mov.b64 %0, {%1, %2};" : "=l"(r) : "f"(lo), "f"(hi)); return r;
}
__device__ __forceinline__ void upk2(ull v, float& lo, float& hi) {
    asm("mov.b64 {%0, %1}, %2;" : "=f"(lo), "=f"(hi) : "l"(v));
}
__device__ __forceinline__ ull fadd2(ull a, ull b) {
    ull r; asm("add.rn.f32x2 %0, %1, %2;" : "=l"(r) : "l"(a), "l"(b)); return r;
}
__device__ __forceinline__ ull fmul2(ull a, ull b) {
    ull r; asm("mul.rn.f32x2 %0, %1, %2;" : "=l"(r) : "l"(a), "l"(b)); return r;
}
__device__ __forceinline__ ull ffma2(ull a, ull b, ull c) {
    ull r; asm("fma.rn.f32x2 %0, %1, %2, %3;" : "=l"(r) : "l"(a), "l"(b), "l"(c)); return r;
}

// ---- fp16 helpers ----
__device__ __forceinline__ unsigned pkh2(float lo, float hi) {
    unsigned r; asm("cvt.rn.f16x2.f32 %0, %1, %2;" : "=r"(r) : "f"(hi), "f"(lo)); return r;
}
__device__ __forceinline__ unsigned hadd2u(unsigned a, unsigned b) {
    unsigned r; asm("add.rn.f16x2 %0, %1, %2;" : "=r"(r) : "r"(a), "r"(b)); return r;
}
__device__ __forceinline__ unsigned hsub2u(unsigned a, unsigned b) {
    unsigned r; asm("sub.rn.f16x2 %0, %1, %2;" : "=r"(r) : "r"(a), "r"(b)); return r;
}
__device__ __forceinline__ ull h2f2(unsigned h) {
    ull r;
    asm("{\n\t"
        ".reg .b16 lo16, hi16;\n\t"
        ".reg .f32 flo, fhi;\n\t"
        "mov.b32 {lo16, hi16}, %1;\n\t"
        "cvt.f32.f16 flo, lo16;\n\t"
        "cvt.f32.f16 fhi, hi16;\n\t"
        "mov.b64 %0, {flo, fhi};\n\t"
        "}" : "=l"(r) : "r"(h));
    return r;
}

__device__ __forceinline__ void cpa8(unsigned dst, const float* src, unsigned sz) {
    asm volatile("cp.async.ca.shared.global [%0], [%1], 8, %2;"
                 :: "r"(dst), "l"(src), "r"(sz) : "memory");
}

__device__ double g_acc;
__device__ unsigned g_cnt;

// ---- W-pass: sliding 5-tap W sums over 8 inputs -> 4 outputs ----
__device__ __forceinline__ void w_task(const char* sl, uint2* r4h, float* r1,
                                       int c0, int c1, int c2, int c3) {
    const float4* pI = reinterpret_cast<const float4*>(sl);
    const float4* pJ = reinterpret_cast<const float4*>(sl + PLANE_BYTES);
    float4 a0 = pI[0], a1 = pI[1];
    float4 b0 = pJ[0], b1 = pJ[1];

    ull v0 = pk2(a0.x, b0.x), v1 = pk2(a0.y, b0.y);
    ull v2 = pk2(a0.z, b0.z), v3 = pk2(a0.w, b0.w);
    ull v4 = pk2(a1.x, b1.x), v5 = pk2(a1.y, b1.y);
    ull v6 = pk2(a1.z, b1.z), v7 = pk2(a1.w, b1.w);

    ull ab = fadd2(fadd2(fadd2(v0, v1), fadd2(v2, v3)), v4);
    ull cd = fmul2(v0, v0);
    cd = ffma2(v1, v1, cd); cd = ffma2(v2, v2, cd);
    cd = ffma2(v3, v3, cd); cd = ffma2(v4, v4, cd);
    float e = a0.x * b0.x;
    e = fmaf(a0.y, b0.y, e); e = fmaf(a0.z, b0.z, e);
    e = fmaf(a0.w, b0.w, e); e = fmaf(a1.x, b1.x, e);

    float fa, fb, fc, fd;
    upk2(ab, fa, fb); upk2(cd, fc, fd);
    r4h[c0] = make_uint2(pkh2(fa, fb), pkh2(fc, fd)); r1[c0] = e;

    ab = fadd2(ab, v5); ab = ffma2(v0, NG2, ab);
    { ull nv = fmul2(v0, NG2); cd = ffma2(v5, v5, cd); cd = ffma2(nv, v0, cd); }
    e = fmaf(a1.y, b1.y, e); e = fmaf(-a0.x, b0.x, e);
    upk2(ab, fa, fb); upk2(cd, fc, fd);
    r4h[c1] = make_uint2(pkh2(fa, fb), pkh2(fc, fd)); r1[c1] = e;

    ab = fadd2(ab, v6); ab = ffma2(v1, NG2, ab);
    { ull nv = fmul2(v1, NG2); cd = ffma2(v6, v6, cd); cd = ffma2(nv, v1, cd); }
    e = fmaf(a1.z, b1.z, e); e = fmaf(-a0.y, b0.y, e);
    upk2(ab, fa, fb); upk2(cd, fc, fd);
    r4h[c2] = make_uint2(pkh2(fa, fb), pkh2(fc, fd)); r1[c2] = e;

    ab = fadd2(ab, v7); ab = ffma2(v2, NG2, ab);
    { ull nv = fmul2(v2, NG2); cd = ffma2(v7, v7, cd); cd = ffma2(nv, v2, cd); }
    e = fmaf(a1.w, b1.w, e); e = fmaf(-a0.z, b0.z, e);
    upk2(ab, fa, fb); upk2(cd, fc, fd);
    r4h[c3] = make_uint2(pkh2(fa, fb), pkh2(fc, fd)); r1[c3] = e;
}

// ---- H-pass + D-ring + emit for one slice: 3 output rows per thread ----
// 7 halo-row reads, sliding 5-tap. ABCD ring slots stored as half2 (exact
// telescoping: subtract the identical rounded value added 5 slices ago).
// E ring and all totals stay fp32.
__device__ __forceinline__ void h_slice3(
    const uint2* R4, const float* R1, int row0, int swc, int k,
    unsigned (&rAB)[5][3], unsigned (&rCD)[5][3], float (&rE)[5][3],
    ull (&tAB)[3], ull (&tCD)[3], float (&tE)[3],
    bool em, float& lcc)
{
    uint2 q0 = R4[(row0 + 0) * RROWH + swc]; float e0 = R1[(row0 + 0) * RROWE + swc];
    uint2 q1 = R4[(row0 + 1) * RROWH + swc]; float e1 = R1[(row0 + 1) * RROWE + swc];
    uint2 q2 = R4[(row0 + 2) * RROWH + swc]; float e2 = R1[(row0 + 2) * RROWE + swc];
    uint2 q3 = R4[(row0 + 3) * RROWH + swc]; float e3 = R1[(row0 + 3) * RROWE + swc];
    uint2 q4 = R4[(row0 + 4) * RROWH + swc]; float e4 = R1[(row0 + 4) * RROWE + swc];
    uint2 q5 = R4[(row0 + 5) * RROWH + swc]; float e5 = R1[(row0 + 5) * RROWE + swc];
    uint2 q6 = R4[(row0 + 6) * RROWH + swc]; float e6 = R1[(row0 + 6) * RROWE + swc];

    unsigned sAB0 = hadd2u(hadd2u(hadd2u(q0.x, q1.x), hadd2u(q2.x, q3.x)), q4.x);
    unsigned sAB1 = hadd2u(sAB0, hsub2u(q5.x, q0.x));
    unsigned sAB2 = hadd2u(sAB1, hsub2u(q6.x, q1.x));
    unsigned sCD0 = hadd2u(hadd2u(hadd2u(q0.y, q1.y), hadd2u(q2.y, q3.y)), q4.y);
    unsigned sCD1 = hadd2u(sCD0, hsub2u(q5.y, q0.y));
    unsigned sCD2 = hadd2u(sCD1, hsub2u(q6.y, q1.y));
    float sE0 = ((e0 + e1) + (e2 + e3)) + e4;
    float sE1 = sE0 + (e5 - e0);
    float sE2 = sE1 + (e6 - e1);

    unsigned sAB[3] = {sAB0, sAB1, sAB2};
    unsigned sCD[3] = {sCD0, sCD1, sCD2};
    float    sE[3]  = {sE0, sE1, sE2};

    #pragma unroll
    for (int r = 0; r < 3; ++r) {
        ull nf = h2f2(sAB[r]);
        ull of = h2f2(rAB[k][r]);
        tAB[r] = fadd2(tAB[r], ffma2(of, NG2, nf));
        rAB[k][r] = sAB[r];

        nf = h2f2(sCD[r]);
        of = h2f2(rCD[k][r]);
        tCD[r] = fadd2(tCD[r], ffma2(of, NG2, nf));
        rCD[k][r] = sCD[r];

        tE[r] += sE[r] - rE[k][r]; rE[k][r] = sE[r];
    }

    if (em) {
        #pragma unroll
        for (int r = 0; r < 3; ++r) {
            float a, b, c, d;
            upk2(tAB[r], a, b);
            upk2(tCD[r], c, d);
            float ai = a * VINV;
            float bi = b * VINV;
            float cross = fmaf(-ai, b, tE[r]);
            float Ivar  = fmaf(-ai, a, c);
            float Jvar  = fmaf(-bi, b, d);
            lcc += __fdividef(cross * cross, fmaf(Ivar, Jvar, EPSV));
        }
    }
}

__global__ __launch_bounds__(NTHREADS, 2)
void ncc_main_kernel(const float* __restrict__ I, const float* __restrict__ J,
                     float* __restrict__ out) {
    extern __shared__ __align__(16) char dynsm[];   // [pair ring | rs4h | rs1 | redbuf]
    uint2* RS4H = reinterpret_cast<uint2*>(dynsm + RS4H_OFF);  // [2][56][RROWH]
    float* RS1  = reinterpret_cast<float*>(dynsm + RS1_OFF);   // [2][56][RROWE]
    float* redbuf = reinterpret_cast<float*>(dynsm + RED_OFF);

    const int tid = threadIdx.x;
    const int tx = tid & 31;
    const int ty = tid >> 5;                 // 0..7 -> output rows 3ty..3ty+2
    const int w0b = blockIdx.x * TILE_W;
    const int h0b = blockIdx.y * TILE_H;
    const int bz  = blockIdx.z;
    const int n   = bz / 3;
    const int c   = bz - 3 * n;              // z-chunk 0..2
    const int z0  = 54 * c;
    const int len = (c == 2) ? 52 : 54;
    const int NS  = len + 4;                 // slices this chunk (58/58/56)
    const int NP  = NS >> 1;                 // pairs (29/29/28)

    const float* __restrict__ Ibase = I + (size_t)n * DD * HW;
    const float* __restrict__ Jbase = J + (size_t)n * DD * HW;

    unsigned dynu32;
    asm("{ .reg .u64 t; cvta.to.shared.u64 t, %1; cvt.u32.u64 %0, t; }"
        : "=r"(dynu32) : "l"(dynsm));

    // ---- staging mapping: I-plane 8B chunks {tid, tid+256}; J reuses +PLANE ----
    int goff[2]; unsigned soff[2];
    #pragma unroll
    for (int t = 0; t < 2; ++t) {
        int e = tid + t * NTHREADS;
        int hh = e / CHUNKS_PER_ROW, cc2 = e - hh * CHUNKS_PER_ROW;
        int gh = h0b - 2 + hh, gw = w0b - 2 + 2 * cc2;
        bool inb = (e < IPLANE_CHUNKS) && (gh >= 0 && gh < HH) && (gw >= 0 && gw < WW - 1);
        goff[t] = inb ? (gh * WW + gw) : -1;
        soff[t] = (unsigned)(hh * ROW_BYTES + 8 * cc2);
    }
    const bool has2 = (tid < IPLANE_CHUNKS - NTHREADS);   // tid < 248

    // ---- W-pass task mapping: 448 tasks/pair; t1 = tid, t2 = 256+tid (tid<192) ----
    int s1 = (tid >= 224) ? 1 : 0;
    int r1i = tid - 224 * s1;
    int whh1 = r1i >> 3, wwg1 = r1i & 7;
    const int oIJ1 = s1 * SLICE_BYTES + whh1 * ROW_BYTES + wwg1 * 16;
    const int rsrow1 = s1 * HALO_H + whh1;
    const int c10 = wwg1, c11 = 8 + (wwg1 ^ 2), c12 = 16 + (wwg1 ^ 4), c13 = 24 + (wwg1 ^ 6);

    int r2i = tid + 32;                       // task 256+tid -> slice 1, row (tid+32)>>3
    int whh2 = r2i >> 3, wwg2 = r2i & 7;
    const int oIJ2 = SLICE_BYTES + whh2 * ROW_BYTES + wwg2 * 16;
    const int rsrow2 = HALO_H + whh2;
    const int c20 = wwg2, c21 = 8 + (wwg2 ^ 2), c22 = 16 + (wwg2 ^ 4), c23 = 24 + (wwg2 ^ 6);
    const bool wt2 = (tid < 192);

    const int swc = 8 * (tx & 3) + ((tx >> 2) ^ (2 * (tx & 3)));
    const int row0 = 3 * ty;

    // ---- pipeline state (ring ABCD in half2; E + totals fp32) ----
    unsigned rAB[5][3] = {{0}}, rCD[5][3] = {{0}};
    float rE[5][3] = {{0}};
    ull tAB[3] = {0,0,0}, tCD[3] = {0,0,0};
    float tE[3] = {0.f, 0.f, 0.f};
    float local_cc = 0.f;

    auto issue_pair = [&](int m0, unsigned dstoff) {
        #pragma unroll
        for (int s = 0; s < 2; ++s) {
            int z = z0 - 2 + m0 + s;
            bool zv = ((unsigned)z < (unsigned)DD);
            int zc = zv ? z : 0;
            const float* pi = Ibase + (size_t)zc * HW;
            const float* pj = Jbase + (size_t)zc * HW;
            unsigned db = dynu32 + dstoff + (unsigned)(s * SLICE_BYTES);
            #pragma unroll
            for (int t = 0; t < 2; ++t) {
                if (t == 0 || has2) {
                    int go = goff[t];
                    unsigned sz = (zv && go >= 0) ? 8u : 0u;
                    int g2 = (go >= 0) ? go : 0;
                    cpa8(db + soff[t], pi + g2, sz);
                    cpa8(db + PLANE_BYTES + soff[t], pj + g2, sz);
                }
            }
        }
        asm volatile("cp.async.commit_group;" ::: "memory");
    };

    // prologue: pair1 (slices 0,1) -> buf0, pair2 (slices 2,3) -> buf1
    issue_pair(0, 0u);
    issue_pair(2, (unsigned)PAIR_BYTES);
    unsigned offW = 0u, offN = PAIR_BYTES, offI = 2u * PAIR_BYTES;

    constexpr int K1[5] = {3, 0, 2, 4, 1};   // (2p-4) mod 5, p = 1+5g+jj
    constexpr int K2[5] = {4, 1, 3, 0, 2};   // (2p-3) mod 5

    for (int g = 0; g < 6; ++g) {
        #pragma unroll
        for (int jj = 0; jj < 5; ++jj) {
            const int p = 1 + 5 * g + jj;

            if (p >= NP) { asm volatile("cp.async.wait_group 0;" ::: "memory"); }
            else         { asm volatile("cp.async.wait_group 1;" ::: "memory"); }
            __syncthreads();     // pair p staged in offW; rs[pb] final; rs[wb] free

            if (p <= NP - 2) issue_pair(2 * p + 2, offI);

            const int pb = p & 1, wb = pb ^ 1;

            // ---- W-pass on pair p (slices 2p-2, 2p-1) -> rs[wb] ----
            if (p <= NP) {
                const char* base = dynsm + offW;
                w_task(base + oIJ1,
                       RS4H + (wb * RS_ROWS + rsrow1) * RROWH,
                       RS1  + (wb * RS_ROWS + rsrow1) * RROWE,
                       c10, c11, c12, c13);
                if (wt2)
                    w_task(base + oIJ2,
                           RS4H + (wb * RS_ROWS + rsrow2) * RROWH,
                           RS1  + (wb * RS_ROWS + rsrow2) * RROWE,
                           c20, c21, c22, c23);
            }

            // ---- H-pass on pair p-1 (slices 2p-4, 2p-3) from rs[pb] ----
            if (p >= 2 && p <= NP + 1) {
                const bool em = (p >= 4);
                const uint2* R4b = RS4H + pb * RS_ROWS * RROWH;
                const float* R1b = RS1  + pb * RS_ROWS * RROWE;
                h_slice3(R4b, R1b, row0, swc, K1[jj],
                         rAB, rCD, rE, tAB, tCD, tE, em, local_cc);
                h_slice3(R4b + HALO_H * RROWH, R1b + HALO_H * RROWE, row0, swc, K2[jj],
                         rAB, rCD, rE, tAB, tCD, tE, em, local_cc);
            }

            unsigned t0 = offW; offW = offN; offN = offI; offI = t0;
        }
    }

    asm volatile("cp.async.wait_group 0;" ::: "memory");

    // ---- block reduction + fused finalize ----
    float v = local_cc;
    #pragma unroll
    for (int off = 16; off > 0; off >>= 1)
        v += __shfl_xor_sync(0xFFFFFFFFu, v, off);
    __syncthreads();
    if (tx == 0) redbuf[ty] = v;
    __syncthreads();
    if (tid == 0) {
        float w = ((redbuf[0] + redbuf[1]) + (redbuf[2] + redbuf[3]))
                + ((redbuf[4] + redbuf[5]) + (redbuf[6] + redbuf[7]));
        atomicAdd(&g_acc, (double)w);
        __threadfence();
        unsigned t = atomicAdd(&g_cnt, 1u);
        if (t == NBLOCKS - 1) {
            double total = *((volatile double*)&g_acc);
            out[0] = (float)(-total / ((double)NN * DD * HH * WW));
            g_acc = 0.0;
            g_cnt = 0u;
        }
    }
}

extern "C" void kernel_launch(void* const* d_in, const int* in_sizes, int n_in,
                              void* d_out, int out_size) {
    const float* I = (const float*)d_in[0];
    const float* J = (const float*)d_in[1];
    float* out = (float*)d_out;

    cudaFuncSetAttribute(ncc_main_kernel,
                         cudaFuncAttributeMaxDynamicSharedMemorySize, DYN_TOTAL);

    dim3 block(NTHREADS);
    dim3 grid(WW / TILE_W, HH / TILE_H, NN * 3);   // 6 x 8 x 6 = 288 blocks
    ncc_main_kernel<<<grid, block, DYN_TOTAL>>>(I, J, out);
}